// round 1
// baseline (speedup 1.0000x reference)
#include <cuda_runtime.h>
#include <cstdint>

// Haar DWT2: input (B=8, C=32, H=512, W=512) fp32
// output (B=8, 4, C=32, H/2=256, W/2=256) fp32, bands order LL, LH, HL, HH.
//
// Each thread: one output row segment of 4 output columns (8 input columns).
// Loads: 2 rows x 2 float4 = 64B. Stores: 4 bands x 1 float4 = 64B.

#define B_DIM 8
#define C_DIM 32
#define H_DIM 512
#define W_DIM 512
#define H2 (H_DIM / 2)      // 256
#define W2 (W_DIM / 2)      // 256
#define WQ (W2 / 4)         // 64 quads of output columns per row

__global__ __launch_bounds__(256)
void haar_dwt2_kernel(const float* __restrict__ in, float* __restrict__ out) {
    // total threads = B*C*H2*WQ = 8*32*256*64 = 4,194,304
    unsigned t = blockIdx.x * blockDim.x + threadIdx.x;

    unsigned wq = t & (WQ - 1);          // 0..63
    unsigned h2 = (t >> 6) & (H2 - 1);   // 0..255
    unsigned c  = (t >> 14) & (C_DIM - 1); // 0..31
    unsigned b  = t >> 19;               // 0..7

    // input row base for (b, c, 2*h2, 8*wq)
    size_t in_base = ((size_t)(b * C_DIM + c) * H_DIM + 2u * h2) * W_DIM + 8u * wq;
    const float4* r0 = (const float4*)(in + in_base);
    const float4* r1 = (const float4*)(in + in_base + W_DIM);

    float4 a0 = r0[0];  // row0 cols 0..3
    float4 a1 = r0[1];  // row0 cols 4..7
    float4 b0 = r1[0];  // row1 cols 0..3
    float4 b1 = r1[1];  // row1 cols 4..7

    float ll[4], lh[4], hl[4], hh[4];

    // unrolled pairs: (x00, x01) from row0, (x10, x11) from row1
    {
        float x00 = a0.x, x01 = a0.y, x10 = b0.x, x11 = b0.y;
        ll[0] = (x00 + x01 + x10 + x11) * 0.5f;
        lh[0] = (x00 + x01 - x10 - x11) * 0.5f;
        hl[0] = (x00 - x01 + x10 - x11) * 0.5f;
        hh[0] = (x00 - x01 - x10 + x11) * 0.5f;
    }
    {
        float x00 = a0.z, x01 = a0.w, x10 = b0.z, x11 = b0.w;
        ll[1] = (x00 + x01 + x10 + x11) * 0.5f;
        lh[1] = (x00 + x01 - x10 - x11) * 0.5f;
        hl[1] = (x00 - x01 + x10 - x11) * 0.5f;
        hh[1] = (x00 - x01 - x10 + x11) * 0.5f;
    }
    {
        float x00 = a1.x, x01 = a1.y, x10 = b1.x, x11 = b1.y;
        ll[2] = (x00 + x01 + x10 + x11) * 0.5f;
        lh[2] = (x00 + x01 - x10 - x11) * 0.5f;
        hl[2] = (x00 - x01 + x10 - x11) * 0.5f;
        hh[2] = (x00 - x01 - x10 + x11) * 0.5f;
    }
    {
        float x00 = a1.z, x01 = a1.w, x10 = b1.z, x11 = b1.w;
        ll[3] = (x00 + x01 + x10 + x11) * 0.5f;
        lh[3] = (x00 + x01 - x10 - x11) * 0.5f;
        hl[3] = (x00 - x01 + x10 - x11) * 0.5f;
        hh[3] = (x00 - x01 - x10 + x11) * 0.5f;
    }

    // output layout: [B, 4, C, H2, W2]
    size_t band_stride = (size_t)C_DIM * H2 * W2;               // per-band within batch
    size_t out_base = ((size_t)b * 4 * C_DIM + c) * ((size_t)H2 * W2)
                      + (size_t)h2 * W2 + 4u * wq;
    // explicit: ((b*4 + k)*C + c)*H2*W2 + h2*W2 + 4*wq
    float4* o_ll = (float4*)(out + ((size_t)(b * 4 + 0) * C_DIM + c) * (H2 * W2) + h2 * W2 + 4u * wq);
    float4* o_lh = (float4*)(out + ((size_t)(b * 4 + 1) * C_DIM + c) * (H2 * W2) + h2 * W2 + 4u * wq);
    float4* o_hl = (float4*)(out + ((size_t)(b * 4 + 2) * C_DIM + c) * (H2 * W2) + h2 * W2 + 4u * wq);
    float4* o_hh = (float4*)(out + ((size_t)(b * 4 + 3) * C_DIM + c) * (H2 * W2) + h2 * W2 + 4u * wq);
    (void)band_stride; (void)out_base;

    *o_ll = make_float4(ll[0], ll[1], ll[2], ll[3]);
    *o_lh = make_float4(lh[0], lh[1], lh[2], lh[3]);
    *o_hl = make_float4(hl[0], hl[1], hl[2], hl[3]);
    *o_hh = make_float4(hh[0], hh[1], hh[2], hh[3]);
}

extern "C" void kernel_launch(void* const* d_in, const int* in_sizes, int n_in,
                              void* d_out, int out_size) {
    const float* in = (const float*)d_in[0];
    float* out = (float*)d_out;
    unsigned total = B_DIM * C_DIM * H2 * WQ;   // 4,194,304 threads
    haar_dwt2_kernel<<<total / 256, 256>>>(in, out);
}